// round 1
// baseline (speedup 1.0000x reference)
#include <cuda_runtime.h>
#include <math.h>

#define BATCH   2
#define SEQ     2048
#define DIM     1024
#define NHEADS  16
#define DH      64
#define NTOK    (BATCH*SEQ)          // 4096
#define QKVC    (3*NHEADS*DH)        // 3072

// -------- scratch (allocation-free: __device__ globals) --------
__device__ float g_xn [(size_t)NTOK * DIM];    // 16 MB
__device__ float g_qkv[(size_t)NTOK * QKVC];   // 48 MB
__device__ float g_gate[NTOK * NHEADS];        // 256 KB
__device__ float g_att[(size_t)NTOK * DIM];    // 16 MB

// ============================================================
// 1) RMSNorm variant: xn = x / ||x||_2 * gamma * sqrt(DIM)
//    one block (256 thr) per token row
// ============================================================
__global__ __launch_bounds__(256) void rmsnorm_k(const float* __restrict__ x,
                                                 const float* __restrict__ gamma)
{
    int t = blockIdx.x;
    const float4* xr = (const float4*)(x + (size_t)t * DIM);
    float4 a = xr[threadIdx.x];
    float ss = a.x*a.x + a.y*a.y + a.z*a.z + a.w*a.w;

    __shared__ float red[8];
    #pragma unroll
    for (int o = 16; o; o >>= 1) ss += __shfl_xor_sync(0xFFFFFFFFu, ss, o);
    if ((threadIdx.x & 31) == 0) red[threadIdx.x >> 5] = ss;
    __syncthreads();
    if (threadIdx.x < 32) {
        float s2 = (threadIdx.x < 8) ? red[threadIdx.x] : 0.0f;
        #pragma unroll
        for (int o = 4; o; o >>= 1) s2 += __shfl_xor_sync(0xFFFFFFFFu, s2, o);
        if (threadIdx.x == 0) red[0] = s2;
    }
    __syncthreads();
    float inv = rsqrtf(red[0]) * 32.0f;  // sqrt(1024) = 32
    const float4* g4 = (const float4*)gamma;
    float4 g = g4[threadIdx.x];
    float4 o4 = make_float4(a.x*inv*g.x, a.y*inv*g.y, a.z*inv*g.z, a.w*inv*g.w);
    ((float4*)(g_xn + (size_t)t * DIM))[threadIdx.x] = o4;
}

// ============================================================
// 2) SGEMM: C[M,N] = A[M,K] @ B[K,N], all row-major fp32.
//    128x128 tile, BK=8, 256 threads, 8x8 per thread (2x2 of 4x4).
// ============================================================
__global__ __launch_bounds__(256) void sgemm_k(const float* __restrict__ A,
                                               const float* __restrict__ Bm,
                                               float* __restrict__ C,
                                               int M, int Nn, int K)
{
    __shared__ float As[8][128];
    __shared__ float Bs[8][128];

    int tid = threadIdx.x;
    int tx = tid & 15, ty = tid >> 4;

    int aRow = tid >> 1;            // 128 rows, 2 thr/row
    int aCol = (tid & 1) * 4;
    int bRow = tid >> 5;            // 8 rows
    int bCol = (tid & 31) * 4;

    const float* Ap = A + (size_t)(blockIdx.y * 128 + aRow) * K + aCol;
    const float* Bp = Bm + (size_t)bRow * Nn + blockIdx.x * 128 + bCol;

    float acc[8][8];
    #pragma unroll
    for (int i = 0; i < 8; i++)
        #pragma unroll
        for (int j = 0; j < 8; j++) acc[i][j] = 0.0f;

    for (int kt = 0; kt < K; kt += 8) {
        float4 a = *(const float4*)Ap;  Ap += 8;
        float4 b = *(const float4*)Bp;  Bp += (size_t)8 * Nn;

        __syncthreads();
        As[aCol+0][aRow] = a.x; As[aCol+1][aRow] = a.y;
        As[aCol+2][aRow] = a.z; As[aCol+3][aRow] = a.w;
        *(float4*)&Bs[bRow][bCol] = b;
        __syncthreads();

        #pragma unroll
        for (int k = 0; k < 8; k++) {
            float ar[8], br[8];
            *(float4*)&ar[0] = *(const float4*)&As[k][ty*4];
            *(float4*)&ar[4] = *(const float4*)&As[k][64 + ty*4];
            *(float4*)&br[0] = *(const float4*)&Bs[k][tx*4];
            *(float4*)&br[4] = *(const float4*)&Bs[k][64 + tx*4];
            #pragma unroll
            for (int i = 0; i < 8; i++)
                #pragma unroll
                for (int j = 0; j < 8; j++)
                    acc[i][j] += ar[i] * br[j];
        }
    }

    int m0 = blockIdx.y * 128, n0 = blockIdx.x * 128;
    #pragma unroll
    for (int i = 0; i < 8; i++) {
        int row = m0 + ((i < 4) ? (ty*4 + i) : (64 + ty*4 + i - 4));
        float* cp = C + (size_t)row * Nn + n0;
        *(float4*)(cp + tx*4)       = *(float4*)&acc[i][0];
        *(float4*)(cp + 64 + tx*4)  = *(float4*)&acc[i][4];
    }
}

// ============================================================
// 3) Gates: gate[t,h] = sigmoid(xn[t,:] @ w_gates[:,h] + b[h])
// ============================================================
__global__ __launch_bounds__(256) void gates_k(const float* __restrict__ wg,
                                               const float* __restrict__ bg)
{
    int t = blockIdx.x;
    int tid = threadIdx.x;
    int h = tid & 15, chunk = tid >> 4;  // 16 chunks of 64
    const float* xr = g_xn + (size_t)t * DIM;
    float acc = 0.0f;
    int d0 = chunk * 64;
    #pragma unroll 8
    for (int d = d0; d < d0 + 64; d++) acc += xr[d] * wg[d * NHEADS + h];

    __shared__ float s[16][16];
    s[chunk][h] = acc;
    __syncthreads();
    if (tid < 16) {
        float v = bg[tid];
        #pragma unroll
        for (int c = 0; c < 16; c++) v += s[c][tid];
        g_gate[t * NHEADS + tid] = 1.0f / (1.0f + expf(-v));
    }
}

// ============================================================
// 4) RoPE (interleaved) applied in-place to q and k planes
// ============================================================
__global__ __launch_bounds__(256) void rope_k(const float* __restrict__ freqs)
{
    int t = blockIdx.x;
    int pos = t & (SEQ - 1);
    for (int p = threadIdx.x; p < 1024; p += 256) {
        int mat = p >> 9;        // 0 = q, 1 = k
        int rem = p & 511;
        int h = rem >> 5;
        int i = rem & 31;
        float f = (float)pos * freqs[i];
        float sn, cs;
        sincosf(f, &sn, &cs);
        float2* ptr = (float2*)(g_qkv + (size_t)t * QKVC + mat * 1024 + h * DH + 2 * i);
        float2 v = *ptr;
        *ptr = make_float2(v.x * cs - v.y * sn, v.y * cs + v.x * sn);
    }
}

// ============================================================
// 5) Flash attention (fp32) + gate in epilogue.
//    grid (SEQ/64, NHEADS, BATCH), 256 threads = 8 warps.
//    Each warp owns 8 q rows; lane owns keys {lane, lane+32} (conflict-free
//    K reads with stride-65 pad) and output dims {2*lane, 2*lane+1}.
// ============================================================
#define ATTN_SMEM_FLOATS (64*64 + 64*65 + 64*64)
__global__ __launch_bounds__(256) void attn_k()
{
    extern __shared__ float smem[];
    float* Qs = smem;                 // 64 x 64
    float* Ks = smem + 64*64;         // 64 x 65 (pad)
    float* Vs = Ks + 64*65;           // 64 x 64

    int qt = blockIdx.x, h = blockIdx.y, b = blockIdx.z;
    int tid = threadIdx.x, warp = tid >> 5, lane = tid & 31;
    int tBase = b * SEQ + qt * 64;
    const float scale = 0.125f;       // 64^-0.5

    // load Q tile (pre-scaled)
    for (int idx = tid; idx < 64 * 16; idx += 256) {
        int r = idx >> 4, c4 = (idx & 15) << 2;
        float4 v = *(const float4*)(g_qkv + (size_t)(tBase + r) * QKVC + h * DH + c4);
        v.x *= scale; v.y *= scale; v.z *= scale; v.w *= scale;
        *(float4*)&Qs[r * 64 + c4] = v;
    }

    float m[8], l[8], o0[8], o1[8], s0[8], s1[8];
    #pragma unroll
    for (int r = 0; r < 8; r++) { m[r] = -INFINITY; l[r] = 0.0f; o0[r] = 0.0f; o1[r] = 0.0f; }

    int r0 = warp * 8;
    int keyA = lane, keyB = 32 + lane;

    for (int kt = 0; kt < SEQ / 64; kt++) {
        __syncthreads();
        int kBase = b * SEQ + kt * 64;
        for (int idx = tid; idx < 64 * 16; idx += 256) {
            int r = idx >> 4, c4 = (idx & 15) << 2;
            float4 kv = *(const float4*)(g_qkv + (size_t)(kBase + r) * QKVC + 1024 + h * DH + c4);
            Ks[r * 65 + c4 + 0] = kv.x; Ks[r * 65 + c4 + 1] = kv.y;
            Ks[r * 65 + c4 + 2] = kv.z; Ks[r * 65 + c4 + 3] = kv.w;
            float4 vv = *(const float4*)(g_qkv + (size_t)(kBase + r) * QKVC + 2048 + h * DH + c4);
            *(float4*)&Vs[r * 64 + c4] = vv;
        }
        __syncthreads();

        // S = Q K^T (per-lane keys keyA/keyB)
        #pragma unroll
        for (int r = 0; r < 8; r++) { s0[r] = 0.0f; s1[r] = 0.0f; }
        #pragma unroll 4
        for (int d = 0; d < 64; d++) {
            float ka = Ks[keyA * 65 + d];
            float kb = Ks[keyB * 65 + d];
            #pragma unroll
            for (int r = 0; r < 8; r++) {
                float q = Qs[(r0 + r) * 64 + d];
                s0[r] += q * ka;
                s1[r] += q * kb;
            }
        }

        // online softmax; reuse s0/s1 as p
        #pragma unroll
        for (int r = 0; r < 8; r++) {
            float mx = fmaxf(s0[r], s1[r]);
            #pragma unroll
            for (int o = 16; o; o >>= 1) mx = fmaxf(mx, __shfl_xor_sync(0xFFFFFFFFu, mx, o));
            float mn = fmaxf(m[r], mx);
            float corr = __expf(m[r] - mn);
            float p0 = __expf(s0[r] - mn);
            float p1 = __expf(s1[r] - mn);
            float rs = p0 + p1;
            #pragma unroll
            for (int o = 16; o; o >>= 1) rs += __shfl_xor_sync(0xFFFFFFFFu, rs, o);
            l[r] = l[r] * corr + rs;
            m[r] = mn;
            o0[r] *= corr; o1[r] *= corr;
            s0[r] = p0; s1[r] = p1;
        }

        // O += P V  (p broadcast via shuffle; lane owns dims 2*lane, 2*lane+1)
        #pragma unroll 2
        for (int k = 0; k < 32; k++) {
            float2 va = *(const float2*)&Vs[k * 64 + lane * 2];
            float2 vb = *(const float2*)&Vs[(k + 32) * 64 + lane * 2];
            #pragma unroll
            for (int r = 0; r < 8; r++) {
                float pa = __shfl_sync(0xFFFFFFFFu, s0[r], k);
                float pb = __shfl_sync(0xFFFFFFFFu, s1[r], k);
                o0[r] += pa * va.x + pb * vb.x;
                o1[r] += pa * va.y + pb * vb.y;
            }
        }
    }

    // epilogue: normalize, gate, store merged-head layout
    #pragma unroll
    for (int r = 0; r < 8; r++) {
        int t = tBase + r0 + r;
        float sc = (1.0f / l[r]) * g_gate[t * NHEADS + h];
        *(float2*)(g_att + (size_t)t * DIM + h * DH + lane * 2) =
            make_float2(o0[r] * sc, o1[r] * sc);
    }
}

// ============================================================
// launcher
// ============================================================
extern "C" void kernel_launch(void* const* d_in, const int* in_sizes, int n_in,
                              void* d_out, int out_size)
{
    const float* x       = (const float*)d_in[0];
    const float* gamma   = (const float*)d_in[1];
    const float* w_qkv   = (const float*)d_in[2];
    const float* w_gates = (const float*)d_in[3];
    const float* b_gates = (const float*)d_in[4];
    const float* w_out   = (const float*)d_in[5];
    const float* freqs   = (const float*)d_in[6];
    float* out = (float*)d_out;

    float *xn_p, *qkv_p, *att_p;
    cudaGetSymbolAddress((void**)&xn_p,  g_xn);
    cudaGetSymbolAddress((void**)&qkv_p, g_qkv);
    cudaGetSymbolAddress((void**)&att_p, g_att);

    cudaFuncSetAttribute(attn_k, cudaFuncAttributeMaxDynamicSharedMemorySize,
                         ATTN_SMEM_FLOATS * (int)sizeof(float));

    rmsnorm_k<<<NTOK, 256>>>(x, gamma);
    sgemm_k<<<dim3(QKVC / 128, NTOK / 128), 256>>>(xn_p, w_qkv, qkv_p, NTOK, QKVC, DIM);
    gates_k<<<NTOK, 256>>>(w_gates, b_gates);
    rope_k<<<NTOK, 256>>>(freqs);
    attn_k<<<dim3(SEQ / 64, NHEADS, BATCH), 256, ATTN_SMEM_FLOATS * sizeof(float)>>>();
    sgemm_k<<<dim3(DIM / 128, NTOK / 128), 256>>>(att_p, w_out, out, NTOK, DIM, DIM);
}